// round 3
// baseline (speedup 1.0000x reference)
#include <cuda_runtime.h>
#include <math.h>

#define NB   32
#define CIN  64
#define COUT 128
#define TT   256
#define V    25
#define ICH  32
#define EPSF 1e-5f

// Scratch (device globals: allocation-free rule)
__device__ float g_h[(size_t)NB*COUT*TT*V];    // BN1+ReLU output (tcn input)
__device__ float g_res[(size_t)NB*COUT*TT*V];  // residual branch
__device__ float g_xm[NB*CIN*V];               // mean over T
__device__ float g_s[NB*ICH*V];                // softmax weights

// ---------------------------------------------------------------------------
// Kernel 1: xm[n,c,v] = mean_t x[n,c,t,v]
// ---------------------------------------------------------------------------
__global__ void k_mean(const float* __restrict__ x) {
    int b = blockIdx.x;                    // n*CIN + c
    const float* xp = x + (size_t)b * TT * V;
    int v = threadIdx.x & 31, tg = threadIdx.x >> 5;   // 8 t-groups
    float s = 0.f;
    if (v < V) {
        for (int t = tg; t < TT; t += 8) s += xp[t*V + v];
    }
    __shared__ float sm[8][32];
    sm[tg][v] = s;
    __syncthreads();
    if (tg == 0 && v < V) {
        float tot = 0.f;
        #pragma unroll
        for (int g = 0; g < 8; g++) tot += sm[g][v];
        g_xm[b*V + v] = tot * (1.f / TT);
    }
}

// ---------------------------------------------------------------------------
// Kernel 2: s[n,i,v] = softmax_v( -(w2@xm + b2) )   (x1 cancels in softmax)
// ---------------------------------------------------------------------------
__global__ void k_soft(const float* __restrict__ w2, const float* __restrict__ b2) {
    int n = blockIdx.x >> 5, i = blockIdx.x & 31;
    int v = threadIdx.x;                   // 32 lanes
    float z = -1e30f;
    if (v < V) {
        float acc = b2[i];
        const float* w  = w2 + i*CIN;
        const float* xm = g_xm + n*CIN*V;
        #pragma unroll 8
        for (int c = 0; c < CIN; c++) acc = fmaf(w[c], xm[c*V + v], acc);
        z = -acc;
    }
    float m = z;
    #pragma unroll
    for (int off = 16; off; off >>= 1) m = fmaxf(m, __shfl_xor_sync(~0u, m, off));
    float e = (v < V) ? expf(z - m) : 0.f;
    float ssum = e;
    #pragma unroll
    for (int off = 16; off; off >>= 1) ssum += __shfl_xor_sync(~0u, ssum, off);
    if (v < V) g_s[(n*ICH + i)*V + v] = e / ssum;
}

// ---------------------------------------------------------------------------
// Kernel 3: fused w3/w4/wr 1x1 convs + y1 (softmax-weighted) + y2 (A-mix)
//           + BN1 + ReLU -> g_h ;  BNr residual -> g_res
// grid (og=2, tgrp=32, n=32), block 256, dyn smem ~106KB
// ---------------------------------------------------------------------------
__global__ void __launch_bounds__(256, 2) k_fuse(
    const float* __restrict__ x,  const float* __restrict__ A,
    const float* __restrict__ w3, const float* __restrict__ b3,
    const float* __restrict__ w4, const float* __restrict__ b4,
    const float* __restrict__ wr, const float* __restrict__ br,
    const float* __restrict__ bn1g, const float* __restrict__ bn1b,
    const float* __restrict__ bn1m, const float* __restrict__ bn1v,
    const float* __restrict__ bnrg, const float* __restrict__ bnrb,
    const float* __restrict__ bnrm, const float* __restrict__ bnrv)
{
    extern __shared__ float sm[];
    float* sx  = sm;            // [CIN][8][V] = 12800
    float* sw3 = sx  + 12800;   // [64][CIN]  = 4096
    float* sw4 = sw3 + 4096;
    float* swr = sw4 + 4096;
    float* ssv = swr + 4096;    // [32][V] = 800
    float* sA  = ssv + 800;     // [V][V]  = 625

    const int og    = blockIdx.x;     // 0..1 (64 output channels each)
    const int tbase = blockIdx.y * 8; // t tile of 8
    const int n     = blockIdx.z;
    const int tid   = threadIdx.x;

    // stage x tile: fully coalesced (contiguous per input channel row)
    for (int idx = tid; idx < 12800; idx += 256) {
        int c = idx / 200, r = idx % 200;  // r = tl*25 + v (contiguous)
        sx[idx] = x[(((size_t)n*CIN + c)*TT + tbase)*V + r];
    }
    for (int idx = tid; idx < 4096; idx += 256) {
        int ol = idx >> 6, c = idx & 63;
        int row = (og*64 + ol)*CIN + c;
        sw3[idx] = w3[row];
        sw4[idx] = w4[row];
        swr[idx] = wr[row];
    }
    for (int idx = tid; idx < 800; idx += 256) ssv[idx] = g_s[n*800 + idx];
    for (int idx = tid; idx < 625; idx += 256) sA[idx]  = A[idx];
    __syncthreads();

    #pragma unroll 1
    for (int p = 0; p < 2; p++) {
        int pi = p*256 + tid;          // 0..511 = 64 ol x 8 tl
        int ol = pi >> 3, tl = pi & 7;
        int o  = og*64 + ol;
        int t  = tbase + tl;

        float p3[V], p4[V], pr[V];
        #pragma unroll
        for (int v = 0; v < V; v++) { p3[v] = 0.f; p4[v] = 0.f; pr[v] = 0.f; }

        const float* xrow = sx + tl*V;
        const float* wrow3 = sw3 + ol*CIN;
        const float* wrow4 = sw4 + ol*CIN;
        const float* wrowr = swr + ol*CIN;
        #pragma unroll 4
        for (int c = 0; c < CIN; c++) {
            float a3 = wrow3[c], a4 = wrow4[c], ar = wrowr[c];
            const float* xp = xrow + c*200;
            #pragma unroll
            for (int v = 0; v < V; v++) {
                float xv = xp[v];
                p3[v] = fmaf(a3, xv, p3[v]);
                p4[v] = fmaf(a4, xv, p4[v]);
                pr[v] = fmaf(ar, xv, pr[v]);
            }
        }

        // y1 = sum_v s[o%32,v]*p3[v] + b3  (sum_v s = 1)
        float y1 = b3[o];
        const float* sv = ssv + (o & 31)*V;
        #pragma unroll
        for (int v = 0; v < V; v++) y1 = fmaf(sv[v], p3[v], y1);

        float b4v = b4[o];
        #pragma unroll
        for (int v = 0; v < V; v++) p4[v] += b4v;

        float s1 = bn1g[o] / sqrtf(bn1v[o] + EPSF);
        float o1 = bn1b[o] - bn1m[o]*s1;
        float sr = bnrg[o] / sqrtf(bnrv[o] + EPSF);
        float orr = bnrb[o] - bnrm[o]*sr;
        float brv = br[o];

        size_t base = (((size_t)n*COUT + o)*TT + t)*V;
        #pragma unroll 5
        for (int u = 0; u < V; u++) {
            float acc = y1;
            const float* Ar = sA + u*V;
            #pragma unroll
            for (int v = 0; v < V; v++) acc = fmaf(Ar[v], p4[v], acc);
            float hv = fmaf(s1, acc, o1);
            g_h[base + u] = hv > 0.f ? hv : 0.f;
        }
        #pragma unroll
        for (int v = 0; v < V; v++)
            g_res[base + v] = fmaf(sr, pr[v] + brv, orr);
    }
}

// ---------------------------------------------------------------------------
// Kernel 4: temporal conv (9,1) pad 4 + bt + BN2 + residual + ReLU -> out
// grid (tgrp=8, ogrp=4, n=32), block 256 = 8 oq x 32 tl, dyn smem ~82KB
// each thread: acc[4 o][25 v], 100 FMA per ~29 shared loads
// ---------------------------------------------------------------------------
__global__ void __launch_bounds__(256) k_tcn(
    const float* __restrict__ wt, const float* __restrict__ bt,
    const float* __restrict__ bn2g, const float* __restrict__ bn2b,
    const float* __restrict__ bn2m, const float* __restrict__ bn2v,
    float* __restrict__ out)
{
    extern __shared__ float sm[];
    float* sh = sm;          // [16 ic][40 t][25 v] = 16000
    float* sw = sm + 16000;  // [32 o][16 ic][9 dt] = 4608

    const int n = blockIdx.z, ogrp = blockIdx.y;
    const int tbase = blockIdx.x * 32;
    const int tid = threadIdx.x;
    const int oq = tid >> 5, tl = tid & 31;   // warp = fixed oq -> w loads broadcast

    float acc[4][V];
    #pragma unroll
    for (int j = 0; j < 4; j++)
        #pragma unroll
        for (int v = 0; v < V; v++) acc[j][v] = 0.f;

    #pragma unroll 1
    for (int ch = 0; ch < 8; ch++) {
        int ib = ch * 16;
        for (int idx = tid; idx < 16000; idx += 256) {
            int i = idx / 1000, r = idx % 1000;
            int tt = r / 25, v = r % 25;
            int gt = tbase + tt - 4;
            float val = 0.f;
            if ((unsigned)gt < TT)
                val = g_h[(((size_t)n*COUT + ib + i)*TT + gt)*V + v];
            sh[idx] = val;
        }
        for (int idx = tid; idx < 4608; idx += 256) {
            int ol = idx / 144, r = idx % 144;  // r = i*9+dt
            sw[idx] = wt[((size_t)(ogrp*32 + ol)*COUT + ib + r/9)*9 + (r % 9)];
        }
        __syncthreads();

        #pragma unroll 1
        for (int i = 0; i < 16; i++) {
            const float* hrow = sh + i*1000 + tl*25;   // lane stride 25: bank-conflict-free
            const float* wrow = sw + (oq*4)*144 + i*9;
            #pragma unroll
            for (int dt = 0; dt < 9; dt++) {
                float w0 = wrow[dt];
                float w1 = wrow[144 + dt];
                float w2 = wrow[288 + dt];
                float w3 = wrow[432 + dt];
                const float* hp = hrow + dt*25;
                #pragma unroll
                for (int v = 0; v < V; v++) {
                    float hv = hp[v];
                    acc[0][v] = fmaf(w0, hv, acc[0][v]);
                    acc[1][v] = fmaf(w1, hv, acc[1][v]);
                    acc[2][v] = fmaf(w2, hv, acc[2][v]);
                    acc[3][v] = fmaf(w3, hv, acc[3][v]);
                }
            }
        }
        __syncthreads();
    }

    int t = tbase + tl;
    #pragma unroll
    for (int j = 0; j < 4; j++) {
        int o = ogrp*32 + oq*4 + j;
        float s2 = bn2g[o] / sqrtf(bn2v[o] + EPSF);
        float o2 = bn2b[o] - bn2m[o]*s2 + s2*bt[o];   // folds +bt into BN2
        size_t base = (((size_t)n*COUT + o)*TT + t)*V;
        #pragma unroll
        for (int v = 0; v < V; v++) {
            float val = fmaf(s2, acc[j][v], o2) + g_res[base + v];
            out[base + v] = val > 0.f ? val : 0.f;
        }
    }
}

// ---------------------------------------------------------------------------
extern "C" void kernel_launch(void* const* d_in, const int* in_sizes, int n_in,
                              void* d_out, int out_size) {
    const float* x    = (const float*)d_in[0];
    const float* A    = (const float*)d_in[1];
    // d_in[2], d_in[3] = w1, b1 -- unused (cancel in softmax)
    const float* w2   = (const float*)d_in[4];
    const float* b2   = (const float*)d_in[5];
    const float* w3   = (const float*)d_in[6];
    const float* b3   = (const float*)d_in[7];
    const float* w4   = (const float*)d_in[8];
    const float* b4   = (const float*)d_in[9];
    const float* bn1g = (const float*)d_in[10];
    const float* bn1b = (const float*)d_in[11];
    const float* bn1m = (const float*)d_in[12];
    const float* bn1v = (const float*)d_in[13];
    const float* wt   = (const float*)d_in[14];
    const float* bt   = (const float*)d_in[15];
    const float* bn2g = (const float*)d_in[16];
    const float* bn2b = (const float*)d_in[17];
    const float* bn2m = (const float*)d_in[18];
    const float* bn2v = (const float*)d_in[19];
    const float* wr   = (const float*)d_in[20];
    const float* br   = (const float*)d_in[21];
    const float* bnrg = (const float*)d_in[22];
    const float* bnrb = (const float*)d_in[23];
    const float* bnrm = (const float*)d_in[24];
    const float* bnrv = (const float*)d_in[25];
    float* out = (float*)d_out;

    static const int FUSE_SMEM = (12800 + 3*4096 + 800 + 625) * 4;   // 106052
    static const int TCN_SMEM  = (16000 + 4608) * 4;                  // 82432
    cudaFuncSetAttribute(k_fuse, cudaFuncAttributeMaxDynamicSharedMemorySize, FUSE_SMEM);
    cudaFuncSetAttribute(k_tcn,  cudaFuncAttributeMaxDynamicSharedMemorySize, TCN_SMEM);

    k_mean<<<NB*CIN, 256>>>(x);
    k_soft<<<NB*ICH, 32>>>(w2, b2);
    k_fuse<<<dim3(2, 32, NB), 256, FUSE_SMEM>>>(
        x, A, w3, b3, w4, b4, wr, br,
        bn1g, bn1b, bn1m, bn1v, bnrg, bnrb, bnrm, bnrv);
    k_tcn<<<dim3(8, 4, NB), 256, TCN_SMEM>>>(
        wt, bt, bn2g, bn2b, bn2m, bn2v, out);
}

// round 6
// speedup vs baseline: 3.5369x; 3.5369x over previous
#include <cuda_runtime.h>
#include <math.h>
#include <stdint.h>

#define NB   32
#define CIN  64
#define COUT 128
#define TT   256
#define V    25
#define ICH  32
#define P    6400          // TT*V flat positions per (n, channel)
#define EPSF 1e-5f

// ---------------------------------------------------------------------------
// Scratch (device globals: allocation-free rule)
// ---------------------------------------------------------------------------
__device__ __align__(16) float g_res[(size_t)NB*COUT*P];   // residual fp32 [n][o][p]
__device__ __align__(16) float g_hT [(size_t)NB*P*COUT];   // h (tf32-rounded) [n][p][c]
__device__ __align__(16) float g_wtT[9*COUT*COUT];         // wt (tf32-rounded) [dt][o][c]
__device__ float g_xm[NB*CIN*V];
__device__ float g_s[NB*ICH*V];

__device__ __forceinline__ float tf32r(float x) {
    uint32_t r;
    asm("cvt.rna.tf32.f32 %0, %1;" : "=r"(r) : "f"(x));
    return __uint_as_float(r);
}

// ---------------------------------------------------------------------------
// Kernel 1: xm[n,c,v] = mean_t x[n,c,t,v]
// ---------------------------------------------------------------------------
__global__ void k_mean(const float* __restrict__ x) {
    int b = blockIdx.x;
    const float* xp = x + (size_t)b * TT * V;
    int v = threadIdx.x & 31, tg = threadIdx.x >> 5;
    float s = 0.f;
    if (v < V) for (int t = tg; t < TT; t += 8) s += xp[t*V + v];
    __shared__ float sm[8][32];
    sm[tg][v] = s;
    __syncthreads();
    if (tg == 0 && v < V) {
        float tot = 0.f;
        #pragma unroll
        for (int g = 0; g < 8; g++) tot += sm[g][v];
        g_xm[b*V + v] = tot * (1.f / TT);
    }
}

// ---------------------------------------------------------------------------
// Kernel 2: s[n,i,v] = softmax_v( -(w2@xm + b2) )   (x1 cancels in softmax)
// ---------------------------------------------------------------------------
__global__ void k_soft(const float* __restrict__ w2, const float* __restrict__ b2) {
    int n = blockIdx.x >> 5, i = blockIdx.x & 31;
    int v = threadIdx.x;
    float z = -1e30f;
    if (v < V) {
        float acc = b2[i];
        const float* w  = w2 + i*CIN;
        const float* xm = g_xm + n*CIN*V;
        #pragma unroll 8
        for (int c = 0; c < CIN; c++) acc = fmaf(w[c], xm[c*V + v], acc);
        z = -acc;
    }
    float m = z;
    #pragma unroll
    for (int off = 16; off; off >>= 1) m = fmaxf(m, __shfl_xor_sync(~0u, m, off));
    float e = (v < V) ? expf(z - m) : 0.f;
    float ssum = e;
    #pragma unroll
    for (int off = 16; off; off >>= 1) ssum += __shfl_xor_sync(~0u, ssum, off);
    if (v < V) g_s[(n*ICH + i)*V + v] = e / ssum;
}

// ---------------------------------------------------------------------------
// Kernel 2b: wt -> [dt][o][c] fp32, tf32-rounded
// ---------------------------------------------------------------------------
__global__ void k_wprep(const float* __restrict__ wt) {
    int idx = blockIdx.x * 256 + threadIdx.x;
    if (idx >= 9*COUT*COUT) return;
    int dt = idx / (COUT*COUT), r = idx % (COUT*COUT);
    int o = r / COUT, c = r % COUT;
    g_wtT[idx] = tf32r(wt[((size_t)o*COUT + c)*9 + dt]);
}

// ---------------------------------------------------------------------------
// Kernel 3: fused w3/w4/wr 1x1 convs + softmax-y1 + A-mix + BN1 + ReLU
//           -> g_hT (tf32-rounded fp32, [n][p][c]) ; BNr residual -> g_res
// grid (og=2, tgrp=32, n=32), block 512
// ---------------------------------------------------------------------------
__global__ void __launch_bounds__(512) k_fuse(
    const float* __restrict__ x,  const float* __restrict__ A,
    const float* __restrict__ w3, const float* __restrict__ b3,
    const float* __restrict__ w4, const float* __restrict__ b4,
    const float* __restrict__ wr, const float* __restrict__ br,
    const float* __restrict__ bn1g, const float* __restrict__ bn1b,
    const float* __restrict__ bn1m, const float* __restrict__ bn1v,
    const float* __restrict__ bnrg, const float* __restrict__ bnrb,
    const float* __restrict__ bnrm, const float* __restrict__ bnrv)
{
    extern __shared__ float sm[];
    float* sx  = sm;            // [CIN][8*25] = 12800
    float* sw3 = sm + 12800;    // [64][65]
    float* sw4 = sm + 16960;
    float* swr = sm + 21120;
    float* ssv = sm + 25280;    // [32][25]
    float* sA  = sm + 26080;    // [25][25]  (26705 floats total)

    const int og    = blockIdx.x;
    const int tbase = blockIdx.y * 8;
    const int n     = blockIdx.z;
    const int tid   = threadIdx.x;

    for (int idx = tid; idx < 12800; idx += 512) {
        int c = idx / 200, r = idx % 200;
        sx[idx] = x[(((size_t)n*CIN + c)*TT + tbase)*V + r];
    }
    for (int idx = tid; idx < 4096; idx += 512) {
        int ol = idx >> 6, c = idx & 63;
        int row = (og*64 + ol)*CIN + c;
        sw3[ol*65 + c] = w3[row];
        sw4[ol*65 + c] = w4[row];
        swr[ol*65 + c] = wr[row];
    }
    for (int idx = tid; idx < 800; idx += 512) ssv[idx] = g_s[n*800 + idx];
    for (int idx = tid; idx < 625; idx += 512) sA[idx]  = A[idx];
    __syncthreads();

    const int ol = tid & 63, tl = tid >> 6;
    const int o  = og*64 + ol;

    float p3[V], p4[V], pr[V];
    #pragma unroll
    for (int v = 0; v < V; v++) { p3[v] = 0.f; p4[v] = 0.f; pr[v] = 0.f; }

    const float* xrow  = sx + tl*V;
    const float* wrow3 = sw3 + ol*65;
    const float* wrow4 = sw4 + ol*65;
    const float* wrowr = swr + ol*65;
    #pragma unroll 4
    for (int c = 0; c < CIN; c++) {
        float a3 = wrow3[c], a4 = wrow4[c], ar = wrowr[c];
        const float* xp = xrow + c*200;
        #pragma unroll
        for (int v = 0; v < V; v++) {
            float xv = xp[v];
            p3[v] = fmaf(a3, xv, p3[v]);
            p4[v] = fmaf(a4, xv, p4[v]);
            pr[v] = fmaf(ar, xv, pr[v]);
        }
    }

    float y1 = b3[o];
    const float* sv = ssv + (o & 31)*V;
    #pragma unroll
    for (int v = 0; v < V; v++) y1 = fmaf(sv[v], p3[v], y1);

    float b4v = b4[o];
    #pragma unroll
    for (int v = 0; v < V; v++) p4[v] += b4v;

    float s1  = bn1g[o] / sqrtf(bn1v[o] + EPSF);
    float o1  = bn1b[o] - bn1m[o]*s1;
    float sr  = bnrg[o] / sqrtf(bnrv[o] + EPSF);
    float orr = bnrb[o] - bnrm[o]*sr;
    float brv = br[o];

    float ph[V];
    #pragma unroll 5
    for (int u = 0; u < V; u++) {
        float acc = y1;
        const float* Ar = sA + u*V;
        #pragma unroll
        for (int v = 0; v < V; v++) acc = fmaf(Ar[v], p4[v], acc);
        float hv = fmaf(s1, acc, o1);
        ph[u] = tf32r(hv > 0.f ? hv : 0.f);
    }
    #pragma unroll
    for (int v = 0; v < V; v++) pr[v] = fmaf(sr, pr[v] + brv, orr);

    // transpose through smem for coalesced stores
    __syncthreads();
    float* res_sh = sm;            // [64][201]
    float* h_sh   = sm + 12864;    // [64][201]
    #pragma unroll
    for (int v = 0; v < V; v++) {
        res_sh[ol*201 + tl*25 + v] = pr[v];
        h_sh [ol*201 + tl*25 + v] = ph[v];
    }
    __syncthreads();

    size_t pb = (size_t)n*P + (size_t)tbase*25;
    for (int idx = tid; idx < 12800; idx += 512) {
        int pl = idx >> 6, oc = idx & 63;
        g_hT[(pb + pl)*COUT + og*64 + oc] = h_sh[oc*201 + pl];
    }
    for (int idx = tid; idx < 12800; idx += 512) {
        int oc = idx / 200, r = idx % 200;
        g_res[((size_t)n*COUT + og*64 + oc)*P + (size_t)tbase*25 + r] = res_sh[oc*201 + r];
    }
}

// ---------------------------------------------------------------------------
// Kernel 4: temporal conv as 9 shifted GEMMs via mma.sync tf32 (HMMA)
// D[p,o] = sum_dt sum_c H[p+(dt-4)*25, c] * Wdt[o, c]
// grid (50 ptiles, 32 n), block 256 = 8 warps (4 M x 2 N), warp tile 32x64
// ---------------------------------------------------------------------------
#define AST 36     // smem stride for A/B tiles (floats): banks = 4g+tg, conflict-free
#define DST 133    // epilogue tile stride (coprime with 32)
#define AROWS 328  // 128 + 8*25 extended rows (covers all 9 shifts)

__device__ __forceinline__ void mma_tf32(float* c, const uint32_t* a, const uint32_t* b) {
    asm volatile(
        "mma.sync.aligned.m16n8k8.row.col.f32.tf32.tf32.f32 "
        "{%0,%1,%2,%3}, {%4,%5,%6,%7}, {%8,%9}, {%0,%1,%2,%3};"
        : "+f"(c[0]), "+f"(c[1]), "+f"(c[2]), "+f"(c[3])
        : "r"(a[0]), "r"(a[1]), "r"(a[2]), "r"(a[3]), "r"(b[0]), "r"(b[1]));
}

__global__ void __launch_bounds__(256, 2) k_tcn_mma(
    const float* __restrict__ bt,
    const float* __restrict__ bn2g, const float* __restrict__ bn2b,
    const float* __restrict__ bn2m, const float* __restrict__ bn2v,
    float* __restrict__ out)
{
    extern __shared__ __align__(16) float dsm[];
    float* As = dsm;                   // [AROWS][AST] = 328*36 = 11808 floats
    float* Bs = dsm + AROWS*AST;       // [128][AST]  = 4608 floats
    __shared__ float s_s2[COUT], s_o2[COUT];

    const int tid = threadIdx.x, wid = tid >> 5, lid = tid & 31;
    const int gq = lid >> 2, tg = lid & 3;     // fragment group / thread-in-group
    const int wm = wid >> 1, wn = wid & 1;     // 4x2 warp grid
    const int n = blockIdx.y;
    const int pbase = blockIdx.x * 128;

    if (tid < COUT) {
        float s2 = bn2g[tid] / sqrtf(bn2v[tid] + EPSF);
        s_s2[tid] = s2;
        s_o2[tid] = bn2b[tid] - bn2m[tid]*s2 + s2*bt[tid];
    }

    float acc[2][8][4];
    #pragma unroll
    for (int mf = 0; mf < 2; mf++)
        #pragma unroll
        for (int nf = 0; nf < 8; nf++)
            #pragma unroll
            for (int q = 0; q < 4; q++) acc[mf][nf][q] = 0.f;

    const float* hbase = g_hT + (size_t)n * P * COUT;

    #pragma unroll 1
    for (int ck = 0; ck < 4; ck++) {
        __syncthreads();   // prior compute done; safe to overwrite A and B
        // stage extended A tile: rows pbase-100 .. pbase+227, cols ck*32..+32
        #pragma unroll 1
        for (int v4 = tid; v4 < AROWS*8; v4 += 256) {
            int r = v4 >> 3, q = v4 & 7;
            int gp = pbase - 100 + r;
            float4 val = make_float4(0.f, 0.f, 0.f, 0.f);
            if ((unsigned)gp < (unsigned)P)
                val = *reinterpret_cast<const float4*>(hbase + (size_t)gp*COUT + ck*32 + q*4);
            *reinterpret_cast<float4*>(As + r*AST + q*4) = val;
        }

        #pragma unroll 1
        for (int dt = 0; dt < 9; dt++) {
            if (dt) __syncthreads();   // prior dt compute done before B overwrite
            #pragma unroll
            for (int i = 0; i < 4; i++) {
                int v4 = tid + i*256;          // 1024 float4 = 128 rows x 8
                int r = v4 >> 3, q = v4 & 7;
                *reinterpret_cast<float4*>(Bs + r*AST + q*4) =
                    *reinterpret_cast<const float4*>(
                        g_wtT + ((size_t)dt*COUT + r)*COUT + ck*32 + q*4);
            }
            __syncthreads();

            const float* Aw = As + (dt*25 + wm*32 + gq)*AST + tg;
            const float* Bw = Bs + (wn*64 + gq)*AST + tg;
            #pragma unroll
            for (int ks = 0; ks < 4; ks++) {
                int k0 = ks*8;
                uint32_t af[2][4];
                #pragma unroll
                for (int mf = 0; mf < 2; mf++) {
                    const float* ap = Aw + mf*16*AST + k0;
                    af[mf][0] = __float_as_uint(ap[0]);
                    af[mf][1] = __float_as_uint(ap[8*AST]);
                    af[mf][2] = __float_as_uint(ap[4]);
                    af[mf][3] = __float_as_uint(ap[8*AST + 4]);
                }
                uint32_t bf[8][2];
                #pragma unroll
                for (int nf = 0; nf < 8; nf++) {
                    const float* bp = Bw + nf*8*AST + k0;
                    bf[nf][0] = __float_as_uint(bp[0]);
                    bf[nf][1] = __float_as_uint(bp[4]);
                }
                #pragma unroll
                for (int mf = 0; mf < 2; mf++)
                    #pragma unroll
                    for (int nf = 0; nf < 8; nf++)
                        mma_tf32(acc[mf][nf], af[mf], bf[nf]);
            }
        }
    }

    // epilogue: transpose D through smem, then coalesced BN2+res+ReLU
    __syncthreads();
    float* Ds = dsm;   // [128 p][DST]
    #pragma unroll
    for (int mf = 0; mf < 2; mf++) {
        int r0 = wm*32 + mf*16 + gq;
        #pragma unroll
        for (int nf = 0; nf < 8; nf++) {
            int c0 = wn*64 + nf*8 + tg*2;
            Ds[r0*DST + c0]       = acc[mf][nf][0];
            Ds[r0*DST + c0 + 1]   = acc[mf][nf][1];
            Ds[(r0+8)*DST + c0]   = acc[mf][nf][2];
            Ds[(r0+8)*DST + c0+1] = acc[mf][nf][3];
        }
    }
    __syncthreads();

    {
        int o = tid >> 1, half = tid & 1;
        float s2 = s_s2[o], o2 = s_o2[o];
        size_t gbase = ((size_t)n*COUT + o)*P + pbase + half*64;
        const float4* rp = reinterpret_cast<const float4*>(g_res + gbase);
        float4*       op = reinterpret_cast<float4*>(out + gbase);
        #pragma unroll 4
        for (int j4 = 0; j4 < 16; j4++) {
            int pl = half*64 + j4*4;
            float4 r = rp[j4];
            float4 w;
            w.x = fmaf(s2, Ds[(pl+0)*DST + o], o2) + r.x;
            w.y = fmaf(s2, Ds[(pl+1)*DST + o], o2) + r.y;
            w.z = fmaf(s2, Ds[(pl+2)*DST + o], o2) + r.z;
            w.w = fmaf(s2, Ds[(pl+3)*DST + o], o2) + r.w;
            w.x = w.x > 0.f ? w.x : 0.f;
            w.y = w.y > 0.f ? w.y : 0.f;
            w.z = w.z > 0.f ? w.z : 0.f;
            w.w = w.w > 0.f ? w.w : 0.f;
            op[j4] = w;
        }
    }
}

// ---------------------------------------------------------------------------
extern "C" void kernel_launch(void* const* d_in, const int* in_sizes, int n_in,
                              void* d_out, int out_size) {
    const float* x    = (const float*)d_in[0];
    const float* A    = (const float*)d_in[1];
    // d_in[2], d_in[3] = w1, b1 -- cancel in softmax
    const float* w2   = (const float*)d_in[4];
    const float* b2   = (const float*)d_in[5];
    const float* w3   = (const float*)d_in[6];
    const float* b3   = (const float*)d_in[7];
    const float* w4   = (const float*)d_in[8];
    const float* b4   = (const float*)d_in[9];
    const float* bn1g = (const float*)d_in[10];
    const float* bn1b = (const float*)d_in[11];
    const float* bn1m = (const float*)d_in[12];
    const float* bn1v = (const float*)d_in[13];
    const float* wt   = (const float*)d_in[14];
    const float* bt   = (const float*)d_in[15];
    const float* bn2g = (const float*)d_in[16];
    const float* bn2b = (const float*)d_in[17];
    const float* bn2m = (const float*)d_in[18];
    const float* bn2v = (const float*)d_in[19];
    const float* wr   = (const float*)d_in[20];
    const float* br   = (const float*)d_in[21];
    const float* bnrg = (const float*)d_in[22];
    const float* bnrb = (const float*)d_in[23];
    const float* bnrm = (const float*)d_in[24];
    const float* bnrv = (const float*)d_in[25];
    float* out = (float*)d_out;

    static const int FUSE_SMEM = 26705 * 4;                      // 106820 B
    static const int TCN_SMEM  = (128*DST > AROWS*AST + 128*AST ?
                                  128*DST : AROWS*AST + 128*AST) * 4;  // 68096 B
    cudaFuncSetAttribute(k_fuse,    cudaFuncAttributeMaxDynamicSharedMemorySize, FUSE_SMEM);
    cudaFuncSetAttribute(k_tcn_mma, cudaFuncAttributeMaxDynamicSharedMemorySize, TCN_SMEM);

    k_mean<<<NB*CIN, 256>>>(x);
    k_soft<<<NB*ICH, 32>>>(w2, b2);
    k_wprep<<<(9*COUT*COUT + 255)/256, 256>>>(wt);
    k_fuse<<<dim3(2, 32, NB), 512, FUSE_SMEM>>>(
        x, A, w3, b3, w4, b4, wr, br,
        bn1g, bn1b, bn1m, bn1v, bnrg, bnrb, bnrm, bnrv);
    k_tcn_mma<<<dim3(50, NB), 256, TCN_SMEM>>>(
        bt, bn2g, bn2b, bn2m, bn2v, out);
}

// round 7
// speedup vs baseline: 3.8355x; 1.0844x over previous
#include <cuda_runtime.h>
#include <math.h>
#include <stdint.h>

#define NB   32
#define CIN  64
#define COUT 128
#define TT   256
#define V    25
#define ICH  32
#define P    6400          // TT*V flat positions per (n, channel)
#define EPSF 1e-5f

// ---------------------------------------------------------------------------
// Scratch (device globals: allocation-free rule)
// ---------------------------------------------------------------------------
__device__ __align__(16) float g_res[(size_t)NB*COUT*P];   // residual fp32 [n][o][p]
__device__ __align__(16) float g_hT [(size_t)NB*P*COUT];   // h (tf32-rounded) [n][p][c]
__device__ __align__(16) float g_wtT[9*COUT*COUT];         // wt (tf32-rounded) [dt][o][c]
__device__ float g_xm[NB*CIN*V];
__device__ float g_s[NB*ICH*V];

__device__ __forceinline__ float tf32r(float x) {
    uint32_t r;
    asm("cvt.rna.tf32.f32 %0, %1;" : "=r"(r) : "f"(x));
    return __uint_as_float(r);
}

__device__ __forceinline__ void mma_tf32(float* c, const uint32_t* a, const uint32_t* b) {
    asm volatile(
        "mma.sync.aligned.m16n8k8.row.col.f32.tf32.tf32.f32 "
        "{%0,%1,%2,%3}, {%4,%5,%6,%7}, {%8,%9}, {%0,%1,%2,%3};"
        : "+f"(c[0]), "+f"(c[1]), "+f"(c[2]), "+f"(c[3])
        : "r"(a[0]), "r"(a[1]), "r"(a[2]), "r"(a[3]), "r"(b[0]), "r"(b[1]));
}

// ---------------------------------------------------------------------------
// Kernel 1: xm[n,c,v] = mean_t x[n,c,t,v]
// ---------------------------------------------------------------------------
__global__ void k_mean(const float* __restrict__ x) {
    int b = blockIdx.x;
    const float* xp = x + (size_t)b * TT * V;
    int v = threadIdx.x & 31, tg = threadIdx.x >> 5;
    float s = 0.f;
    if (v < V) for (int t = tg; t < TT; t += 8) s += xp[t*V + v];
    __shared__ float sm[8][32];
    sm[tg][v] = s;
    __syncthreads();
    if (tg == 0 && v < V) {
        float tot = 0.f;
        #pragma unroll
        for (int g = 0; g < 8; g++) tot += sm[g][v];
        g_xm[b*V + v] = tot * (1.f / TT);
    }
}

// ---------------------------------------------------------------------------
// Kernel 2: s[n,i,v] = softmax_v( -(w2@xm + b2) )   (x1 cancels in softmax)
// ---------------------------------------------------------------------------
__global__ void k_soft(const float* __restrict__ w2, const float* __restrict__ b2) {
    int n = blockIdx.x >> 5, i = blockIdx.x & 31;
    int v = threadIdx.x;
    float z = -1e30f;
    if (v < V) {
        float acc = b2[i];
        const float* w  = w2 + i*CIN;
        const float* xm = g_xm + n*CIN*V;
        #pragma unroll 8
        for (int c = 0; c < CIN; c++) acc = fmaf(w[c], xm[c*V + v], acc);
        z = -acc;
    }
    float m = z;
    #pragma unroll
    for (int off = 16; off; off >>= 1) m = fmaxf(m, __shfl_xor_sync(~0u, m, off));
    float e = (v < V) ? expf(z - m) : 0.f;
    float ssum = e;
    #pragma unroll
    for (int off = 16; off; off >>= 1) ssum += __shfl_xor_sync(~0u, ssum, off);
    if (v < V) g_s[(n*ICH + i)*V + v] = e / ssum;
}

// ---------------------------------------------------------------------------
// Kernel 2b: wt -> [dt][o][c] fp32, tf32-rounded
// ---------------------------------------------------------------------------
__global__ void k_wprep(const float* __restrict__ wt) {
    int idx = blockIdx.x * 256 + threadIdx.x;
    if (idx >= 9*COUT*COUT) return;
    int dt = idx / (COUT*COUT), r = idx % (COUT*COUT);
    int o = r / COUT, c = r % COUT;
    g_wtT[idx] = tf32r(wt[((size_t)o*COUT + c)*9 + dt]);
}

// ---------------------------------------------------------------------------
// Kernel 3: front end on tensor cores.
// Per block (n, ptile of 100 = 4 t-rows): GEMM Y[100(pad128), 384] =
//   X^T[100,64] x [w3;w4;wr]^T, then in-block epilogue: softmax-y1, A-mix,
//   BN1+ReLU -> g_hT (transposed, tf32), BNr residual -> g_res.
// 512 threads = 16 warps (2M x 8N), warp tile 64x48, K=64 single stage.
// ---------------------------------------------------------------------------
#define KST 68     // A/B smem stride (floats): 68 mod 32 = 4 -> frag loads conflict-free
#define YST 389    // Y smem stride: 5*gq+2*tg unique mod 32 -> conflict-free frag stores
#define HST 132    // H smem stride

__global__ void __launch_bounds__(512, 1) k_front(
    const float* __restrict__ x,  const float* __restrict__ A,
    const float* __restrict__ w3, const float* __restrict__ b3,
    const float* __restrict__ w4, const float* __restrict__ b4,
    const float* __restrict__ wr, const float* __restrict__ br,
    const float* __restrict__ bn1g, const float* __restrict__ bn1b,
    const float* __restrict__ bn1m, const float* __restrict__ bn1v,
    const float* __restrict__ bnrg, const float* __restrict__ bnrb,
    const float* __restrict__ bnrm, const float* __restrict__ bnrv)
{
    extern __shared__ __align__(16) float dsm[];
    __shared__ float sA[625], ss[800];
    __shared__ float sb3[128], sb4[128], sc1[128], so1[128], scr[128], sofr[128];

    const int tid = threadIdx.x;
    const int n = blockIdx.y;
    const int pbase = blockIdx.x * 100;

    // per-o constants
    for (int idx = tid; idx < 625; idx += 512) sA[idx] = A[idx];
    for (int idx = tid; idx < 800; idx += 512) ss[idx] = g_s[n*800 + idx];
    if (tid < 128) {
        float s1 = bn1g[tid] / sqrtf(bn1v[tid] + EPSF);
        sc1[tid] = s1;
        so1[tid] = bn1b[tid] - bn1m[tid]*s1;
        float sr = bnrg[tid] / sqrtf(bnrv[tid] + EPSF);
        scr[tid] = sr;
        sofr[tid] = sr*br[tid] + (bnrb[tid] - bnrm[tid]*sr);
        sb3[tid] = b3[tid];
        sb4[tid] = b4[tid];
    }

    float* As = dsm;               // [128][KST]
    float* Bs = dsm + 128*KST;     // [384][KST]

    // stage A = X^T (transpose during store); rows 100..127 zero
    const float* xn = x + (size_t)n*CIN*P + pbase;
    for (int idx = tid; idx < 1600; idx += 512) {
        int c = idx / 25, q = idx % 25;
        float4 v = *reinterpret_cast<const float4*>(xn + (size_t)c*P + q*4);
        int r = q*4;
        As[(r+0)*KST + c] = v.x;
        As[(r+1)*KST + c] = v.y;
        As[(r+2)*KST + c] = v.z;
        As[(r+3)*KST + c] = v.w;
    }
    for (int idx = tid; idx < 28*KST; idx += 512) As[100*KST + idx] = 0.f;

    // stage B = [w3; w4; wr], each [128][64] row-major
    for (int idx = tid; idx < 2048; idx += 512) {
        int r = idx >> 4, q = idx & 15;
        *reinterpret_cast<float4*>(&Bs[r*KST + q*4]) =
            *reinterpret_cast<const float4*>(w3 + r*64 + q*4);
        *reinterpret_cast<float4*>(&Bs[(128 + r)*KST + q*4]) =
            *reinterpret_cast<const float4*>(w4 + r*64 + q*4);
        *reinterpret_cast<float4*>(&Bs[(256 + r)*KST + q*4]) =
            *reinterpret_cast<const float4*>(wr + r*64 + q*4);
    }
    __syncthreads();

    // MMA: 16 warps 2M x 8N, warp tile 64 x 48
    const int wid = tid >> 5, lid = tid & 31;
    const int gq = lid >> 2, tg = lid & 3;
    const int wm = wid >> 3, wn = wid & 7;

    float acc[4][6][4];
    #pragma unroll
    for (int mf = 0; mf < 4; mf++)
        #pragma unroll
        for (int nf = 0; nf < 6; nf++)
            #pragma unroll
            for (int q = 0; q < 4; q++) acc[mf][nf][q] = 0.f;

    const float* Ab = As + (wm*64 + gq)*KST + tg;
    const float* Bb = Bs + (wn*48 + gq)*KST + tg;
    #pragma unroll
    for (int ks = 0; ks < 8; ks++) {
        int k0 = ks*8;
        uint32_t af[4][4];
        #pragma unroll
        for (int mf = 0; mf < 4; mf++) {
            const float* ap = Ab + mf*16*KST + k0;
            af[mf][0] = __float_as_uint(ap[0]);
            af[mf][1] = __float_as_uint(ap[8*KST]);
            af[mf][2] = __float_as_uint(ap[4]);
            af[mf][3] = __float_as_uint(ap[8*KST + 4]);
        }
        #pragma unroll
        for (int nf = 0; nf < 6; nf++) {
            const float* bp = Bb + nf*8*KST + k0;
            uint32_t bf[2];
            bf[0] = __float_as_uint(bp[0]);
            bf[1] = __float_as_uint(bp[4]);
            #pragma unroll
            for (int mf = 0; mf < 4; mf++) mma_tf32(acc[mf][nf], af[mf], bf);
        }
    }
    __syncthreads();   // staging consumed

    // frags -> Y[100][YST]
    float* Ys = dsm;
    float* Hs = dsm + 100*YST;
    #pragma unroll
    for (int mf = 0; mf < 4; mf++) {
        int r0 = wm*64 + mf*16 + gq;
        #pragma unroll
        for (int nf = 0; nf < 6; nf++) {
            int c0 = wn*48 + nf*8 + tg*2;
            if (r0 < 100) {
                Ys[r0*YST + c0]     = acc[mf][nf][0];
                Ys[r0*YST + c0 + 1] = acc[mf][nf][1];
            }
            if (r0 + 8 < 100) {
                Ys[(r0+8)*YST + c0]     = acc[mf][nf][2];
                Ys[(r0+8)*YST + c0 + 1] = acc[mf][nf][3];
            }
        }
    }
    __syncthreads();

    // epilogue: thread = (o, t), t in 0..3
    {
        const int o = tid & 127, t = tid >> 7;
        float p3[V], p4[V], pr[V];
        const float* yrow = Ys + (t*25)*YST;
        float b4v = sb4[o];
        #pragma unroll
        for (int v = 0; v < V; v++) {
            p3[v] = yrow[v*YST + o];
            p4[v] = yrow[v*YST + 128 + o] + b4v;
            pr[v] = yrow[v*YST + 256 + o];
        }
        float y1 = sb3[o];
        const float* sv = ss + (o & 31)*V;
        #pragma unroll
        for (int v = 0; v < V; v++) y1 = fmaf(sv[v], p3[v], y1);

        float s1 = sc1[o], o1 = so1[o];
        #pragma unroll 5
        for (int u = 0; u < V; u++) {
            float a = y1;
            const float* Ar = sA + u*V;
            #pragma unroll
            for (int v = 0; v < V; v++) a = fmaf(Ar[v], p4[v], a);
            float h = fmaf(s1, a, o1);
            Hs[(t*25 + u)*HST + o] = h > 0.f ? h : 0.f;
        }
        float sr = scr[o], ofr = sofr[o];
        float* resp = g_res + ((size_t)n*COUT + o)*P + pbase + t*25;
        #pragma unroll
        for (int v = 0; v < V; v++) resp[v] = fmaf(sr, pr[v], ofr);
    }
    __syncthreads();

    // drain H -> g_hT (coalesced, tf32-rounded)
    float* hdst = g_hT + ((size_t)n*P + pbase)*COUT;
    for (int idx = tid; idx < 3200; idx += 512) {
        int r = idx >> 5, q = idx & 31;
        float4 v = *reinterpret_cast<float4*>(&Hs[r*HST + q*4]);
        v.x = tf32r(v.x); v.y = tf32r(v.y); v.z = tf32r(v.z); v.w = tf32r(v.w);
        *reinterpret_cast<float4*>(&hdst[(size_t)r*COUT + q*4]) = v;
    }
}

// ---------------------------------------------------------------------------
// Kernel 4: temporal conv as 9 shifted GEMMs via mma.sync tf32 (unchanged)
// ---------------------------------------------------------------------------
#define AST 36
#define DST 133
#define AROWS 328

__global__ void __launch_bounds__(256, 2) k_tcn_mma(
    const float* __restrict__ bt,
    const float* __restrict__ bn2g, const float* __restrict__ bn2b,
    const float* __restrict__ bn2m, const float* __restrict__ bn2v,
    float* __restrict__ out)
{
    extern __shared__ __align__(16) float dsm[];
    float* As = dsm;                   // [AROWS][AST]
    float* Bs = dsm + AROWS*AST;       // [128][AST]
    __shared__ float s_s2[COUT], s_o2[COUT];

    const int tid = threadIdx.x, wid = tid >> 5, lid = tid & 31;
    const int gq = lid >> 2, tg = lid & 3;
    const int wm = wid >> 1, wn = wid & 1;
    const int n = blockIdx.y;
    const int pbase = blockIdx.x * 128;

    if (tid < COUT) {
        float s2 = bn2g[tid] / sqrtf(bn2v[tid] + EPSF);
        s_s2[tid] = s2;
        s_o2[tid] = bn2b[tid] - bn2m[tid]*s2 + s2*bt[tid];
    }

    float acc[2][8][4];
    #pragma unroll
    for (int mf = 0; mf < 2; mf++)
        #pragma unroll
        for (int nf = 0; nf < 8; nf++)
            #pragma unroll
            for (int q = 0; q < 4; q++) acc[mf][nf][q] = 0.f;

    const float* hbase = g_hT + (size_t)n * P * COUT;

    #pragma unroll 1
    for (int ck = 0; ck < 4; ck++) {
        __syncthreads();
        #pragma unroll 1
        for (int v4 = tid; v4 < AROWS*8; v4 += 256) {
            int r = v4 >> 3, q = v4 & 7;
            int gp = pbase - 100 + r;
            float4 val = make_float4(0.f, 0.f, 0.f, 0.f);
            if ((unsigned)gp < (unsigned)P)
                val = *reinterpret_cast<const float4*>(hbase + (size_t)gp*COUT + ck*32 + q*4);
            *reinterpret_cast<float4*>(As + r*AST + q*4) = val;
        }

        #pragma unroll 1
        for (int dt = 0; dt < 9; dt++) {
            if (dt) __syncthreads();
            #pragma unroll
            for (int i = 0; i < 4; i++) {
                int v4 = tid + i*256;
                int r = v4 >> 3, q = v4 & 7;
                *reinterpret_cast<float4*>(Bs + r*AST + q*4) =
                    *reinterpret_cast<const float4*>(
                        g_wtT + ((size_t)dt*COUT + r)*COUT + ck*32 + q*4);
            }
            __syncthreads();

            const float* Aw = As + (dt*25 + wm*32 + gq)*AST + tg;
            const float* Bw = Bs + (wn*64 + gq)*AST + tg;
            #pragma unroll
            for (int ks = 0; ks < 4; ks++) {
                int k0 = ks*8;
                uint32_t af[2][4];
                #pragma unroll
                for (int mf = 0; mf < 2; mf++) {
                    const float* ap = Aw + mf*16*AST + k0;
                    af[mf][0] = __float_as_uint(ap[0]);
                    af[mf][1] = __float_as_uint(ap[8*AST]);
                    af[mf][2] = __float_as_uint(ap[4]);
                    af[mf][3] = __float_as_uint(ap[8*AST + 4]);
                }
                uint32_t bf[8][2];
                #pragma unroll
                for (int nf = 0; nf < 8; nf++) {
                    const float* bp = Bw + nf*8*AST + k0;
                    bf[nf][0] = __float_as_uint(bp[0]);
                    bf[nf][1] = __float_as_uint(bp[4]);
                }
                #pragma unroll
                for (int mf = 0; mf < 2; mf++)
                    #pragma unroll
                    for (int nf = 0; nf < 8; nf++)
                        mma_tf32(acc[mf][nf], af[mf], bf[nf]);
            }
        }
    }

    __syncthreads();
    float* Ds = dsm;   // [128 p][DST]
    #pragma unroll
    for (int mf = 0; mf < 2; mf++) {
        int r0 = wm*32 + mf*16 + gq;
        #pragma unroll
        for (int nf = 0; nf < 8; nf++) {
            int c0 = wn*64 + nf*8 + tg*2;
            Ds[r0*DST + c0]       = acc[mf][nf][0];
            Ds[r0*DST + c0 + 1]   = acc[mf][nf][1];
            Ds[(r0+8)*DST + c0]   = acc[mf][nf][2];
            Ds[(r0+8)*DST + c0+1] = acc[mf][nf][3];
        }
    }
    __syncthreads();

    {
        int o = tid >> 1, half = tid & 1;
        float s2 = s_s2[o], o2 = s_o2[o];
        size_t gbase = ((size_t)n*COUT + o)*P + pbase + half*64;
        const float4* rp = reinterpret_cast<const float4*>(g_res + gbase);
        float4*       op = reinterpret_cast<float4*>(out + gbase);
        #pragma unroll 4
        for (int j4 = 0; j4 < 16; j4++) {
            int pl = half*64 + j4*4;
            float4 r = rp[j4];
            float4 w;
            w.x = fmaf(s2, Ds[(pl+0)*DST + o], o2) + r.x;
            w.y = fmaf(s2, Ds[(pl+1)*DST + o], o2) + r.y;
            w.z = fmaf(s2, Ds[(pl+2)*DST + o], o2) + r.z;
            w.w = fmaf(s2, Ds[(pl+3)*DST + o], o2) + r.w;
            w.x = w.x > 0.f ? w.x : 0.f;
            w.y = w.y > 0.f ? w.y : 0.f;
            w.z = w.z > 0.f ? w.z : 0.f;
            w.w = w.w > 0.f ? w.w : 0.f;
            op[j4] = w;
        }
    }
}

// ---------------------------------------------------------------------------
extern "C" void kernel_launch(void* const* d_in, const int* in_sizes, int n_in,
                              void* d_out, int out_size) {
    const float* x    = (const float*)d_in[0];
    const float* A    = (const float*)d_in[1];
    // d_in[2], d_in[3] = w1, b1 -- cancel in softmax
    const float* w2   = (const float*)d_in[4];
    const float* b2   = (const float*)d_in[5];
    const float* w3   = (const float*)d_in[6];
    const float* b3   = (const float*)d_in[7];
    const float* w4   = (const float*)d_in[8];
    const float* b4   = (const float*)d_in[9];
    const float* bn1g = (const float*)d_in[10];
    const float* bn1b = (const float*)d_in[11];
    const float* bn1m = (const float*)d_in[12];
    const float* bn1v = (const float*)d_in[13];
    const float* wt   = (const float*)d_in[14];
    const float* bt   = (const float*)d_in[15];
    const float* bn2g = (const float*)d_in[16];
    const float* bn2b = (const float*)d_in[17];
    const float* bn2m = (const float*)d_in[18];
    const float* bn2v = (const float*)d_in[19];
    const float* wr   = (const float*)d_in[20];
    const float* br   = (const float*)d_in[21];
    const float* bnrg = (const float*)d_in[22];
    const float* bnrb = (const float*)d_in[23];
    const float* bnrm = (const float*)d_in[24];
    const float* bnrv = (const float*)d_in[25];
    float* out = (float*)d_out;

    static const int FRONT_SMEM = (100*YST + 100*HST) * 4;        // 208400 B
    static const int TCN_SMEM   = (128*DST > AROWS*AST + 128*AST ?
                                   128*DST : AROWS*AST + 128*AST) * 4;  // 68096 B
    cudaFuncSetAttribute(k_front,   cudaFuncAttributeMaxDynamicSharedMemorySize, FRONT_SMEM);
    cudaFuncSetAttribute(k_tcn_mma, cudaFuncAttributeMaxDynamicSharedMemorySize, TCN_SMEM);

    k_mean<<<NB*CIN, 256>>>(x);
    k_soft<<<NB*ICH, 32>>>(w2, b2);
    k_wprep<<<(9*COUT*COUT + 255)/256, 256>>>(wt);
    k_front<<<dim3(64, NB), 512, FRONT_SMEM>>>(
        x, A, w3, b3, w4, b4, wr, br,
        bn1g, bn1b, bn1m, bn1v, bnrg, bnrb, bnrm, bnrv);
    k_tcn_mma<<<dim3(50, NB), 256, TCN_SMEM>>>(
        bt, bn2g, bn2b, bn2m, bn2v, out);
}